// round 5
// baseline (speedup 1.0000x reference)
#include <cuda_runtime.h>
#include <cstdint>
#include <math.h>

#define T_LEN 2048
#define BSZ   32
#define DIM   256
#define HID   256
#define LAY   2

typedef unsigned long long ull;

// Scratch: gx[t][l][gate3][b][h]  (2048*2*3*32*256 floats = 402MB)
__device__ float g_gx[(size_t)T_LEN * LAY * 3 * BSZ * HID];

__device__ __forceinline__ void ffma2(ull& d, ull a, ull b) {
    asm("fma.rn.f32x2 %0, %1, %2, %0;" : "+l"(d) : "l"(a), "l"(b));
}
__device__ __forceinline__ ull splat2(float v) {
    ull r; asm("mov.b64 %0, {%1, %1};" : "=l"(r) : "f"(v)); return r;
}
__device__ __forceinline__ float2 unpack2(ull v) {
    float2 r; asm("mov.b64 {%0, %1}, %2;" : "=f"(r.x), "=f"(r.y) : "l"(v)); return r;
}

// ---------------------------------------------------------------------------
// Kernel 1: gx GEMM. 128m x 64n block, 8m x 4n thread tile, full K in smem.
//   C[m][n] = sum_k x[m][k]*Wx[n][k] + bx[n]; scatter into g_gx[t][l][g3][b][h]
// ---------------------------------------------------------------------------
#define APAD 260

__global__ __launch_bounds__(256, 1)
void gx_gemm_kernel(const float* __restrict__ x, const float* __restrict__ Wx,
                    const float* __restrict__ bx)
{
    extern __shared__ float sm1[];
    float* sA = sm1;               // [128][APAD]
    float* sB = sm1 + 128 * APAD;  // [64][APAD]

    const int tid = threadIdx.x;
    const int tx  = tid & 15;      // n group
    const int ty  = tid >> 4;      // m group (8 rows each)
    const int nbase = blockIdx.x * 64;

    // load B panel (64 n-rows x 256 k) once
    for (int idx = tid; idx < 64 * 64; idx += 256) {
        int j = idx >> 6, k4 = idx & 63;
        float4 v = *reinterpret_cast<const float4*>(
            Wx + (((size_t)(nbase + j)) << 8) + (k4 << 2));
        *reinterpret_cast<float4*>(sB + j * APAD + (k4 << 2)) = v;
    }

    int   ncol[4];
    float bias[4];
#pragma unroll
    for (int jj = 0; jj < 4; jj++) {
        ncol[jj] = nbase + tx + 16 * jj;
        bias[jj] = bx[ncol[jj]];
    }
    __syncthreads();

    for (int ms = 0; ms < 4; ms++) {
        const int mbase = (blockIdx.y * 4 + ms) * 128;
        for (int idx = tid; idx < 128 * 64; idx += 256) {
            int r = idx >> 6, k4 = idx & 63;
            float4 v = *reinterpret_cast<const float4*>(
                x + (((size_t)(mbase + r)) << 8) + (k4 << 2));
            *reinterpret_cast<float4*>(sA + r * APAD + (k4 << 2)) = v;
        }
        __syncthreads();

        ull acc2[8][4];
#pragma unroll
        for (int i = 0; i < 8; i++)
#pragma unroll
            for (int j = 0; j < 4; j++) acc2[i][j] = 0ull;

#pragma unroll 2
        for (int k4 = 0; k4 < 64; k4++) {
            ulonglong2 av[8], bv[4];
#pragma unroll
            for (int ii = 0; ii < 8; ii++)
                av[ii] = *reinterpret_cast<const ulonglong2*>(sA + (ty * 8 + ii) * APAD + (k4 << 2));
#pragma unroll
            for (int jj = 0; jj < 4; jj++)
                bv[jj] = *reinterpret_cast<const ulonglong2*>(sB + (tx + 16 * jj) * APAD + (k4 << 2));
#pragma unroll
            for (int ii = 0; ii < 8; ii++)
#pragma unroll
                for (int jj = 0; jj < 4; jj++) {
                    ffma2(acc2[ii][jj], av[ii].x, bv[jj].x);
                    ffma2(acc2[ii][jj], av[ii].y, bv[jj].y);
                }
        }

#pragma unroll
        for (int jj = 0; jj < 4; jj++) {
            const int n  = ncol[jj];
            const int l  = n / 768;
            const int rr = n - l * 768;
            const int g3 = rr >> 8;
            const int h  = rr & 255;
#pragma unroll
            for (int ii = 0; ii < 8; ii++) {
                const int m = mbase + ty * 8 + ii;
                const int b = m >> 11;
                const int t = m & 2047;
                float2 s = unpack2(acc2[ii][jj]);
                const size_t o =
                    ((((size_t)t * LAY + l) * 3 + g3) * BSZ + b) * HID + h;
                g_gx[o] = s.x + s.y + bias[jj];
            }
        }
        __syncthreads();
    }
}

// ---------------------------------------------------------------------------
// Kernel 2: cluster-persistent GRU scan, split-K register tiled, mbarrier sync.
// 128 CTAs = 4 groups x 8 batch-chunks x 4-CTA cluster. 256 threads.
// Warp (rg,kc): rows rg*96 + lane*3 + {0,1,2}, k-chunk kc*64..+63.
// Combine: 128 threads, each owns (h=rank*64+li, batch pair half*2..+1),
// computes r/z/n/h locally, broadcasts h via st.shared::cluster + release
// mbarrier arrive; all threads acquire-wait parity.
// ---------------------------------------------------------------------------
#define SC_THREADS 256
#define SW3_F   (2 * 256 * 32)          // 16384 floats
#define PART_F  (4 * 192 * 2)           //  1536 floats (per half-plane)
#define HBUF_F  (2 * 256 * 4)           //  2048 floats
#define SMEM2_F (SW3_F + 2 * PART_F + HBUF_F)
#define MBAR_OFF (SMEM2_F * 4)          // byte offset of mbarrier (8B aligned)

__device__ __forceinline__ void st_cluster_v2(uint32_t saddr, int trank, float v0, float v1)
{
    uint32_t ra;
    asm volatile("mapa.shared::cluster.u32 %0, %1, %2;" : "=r"(ra) : "r"(saddr), "r"(trank));
    asm volatile("st.shared::cluster.v2.f32 [%0], {%1, %2};" :: "r"(ra), "f"(v0), "f"(v1) : "memory");
}
__device__ __forceinline__ void mbar_init(uint32_t a, uint32_t cnt) {
    asm volatile("mbarrier.init.shared.b64 [%0], %1;" :: "r"(a), "r"(cnt) : "memory");
}
__device__ __forceinline__ void mbar_arrive_remote(uint32_t a, int trank, uint32_t cnt) {
    uint32_t ra;
    asm volatile("mapa.shared::cluster.u32 %0, %1, %2;" : "=r"(ra) : "r"(a), "r"(trank));
    asm volatile("mbarrier.arrive.release.cluster.shared::cluster.b64 _, [%0], %1;"
                 :: "r"(ra), "r"(cnt) : "memory");
}
__device__ __forceinline__ void mbar_wait(uint32_t a, uint32_t par) {
    uint32_t done;
    asm volatile("{\n\t.reg .pred p;\n\t"
                 "mbarrier.try_wait.parity.acquire.cluster.shared::cta.b64 p, [%1], %2;\n\t"
                 "selp.b32 %0, 1, 0, p;\n\t}"
                 : "=r"(done) : "r"(a), "r"(par) : "memory");
    while (!done) {
        asm volatile("{\n\t.reg .pred p;\n\t"
                     "mbarrier.try_wait.parity.acquire.cluster.shared::cta.b64 p, [%1], %2, 0x989680;\n\t"
                     "selp.b32 %0, 1, 0, p;\n\t}"
                     : "=r"(done) : "r"(a), "r"(par) : "memory");
    }
}
__device__ __forceinline__ void cluster_barrier()
{
    asm volatile("barrier.cluster.arrive.aligned;\n\tbarrier.cluster.wait.aligned;" ::: "memory");
}
__device__ __forceinline__ float sig_fast(float x) {
    return __fdividef(1.f, 1.f + __expf(-x));
}
__device__ __forceinline__ float tanh_fast(float x) {
    x = fminf(fmaxf(x, -15.f), 15.f);
    float e = __expf(2.f * x);
    return __fdividef(e - 1.f, e + 1.f);
}

__global__ void __cluster_dims__(4, 1, 1) __launch_bounds__(SC_THREADS, 1)
gru_scan_kernel(const float* __restrict__ Wh, const float* __restrict__ bh,
                float* __restrict__ out)
{
    extern __shared__ float sm[];
    float* sw3   = sm;                  // [2 rg][256 k][32 lane]
    float* partA = sw3 + SW3_F;         // [4 kc][192 rr] float2 (b0,b1)
    float* partB = partA + PART_F;      // [4 kc][192 rr] float2 (b2,b3)
    float* hbuf  = partB + PART_F;      // [2 p][256 k][4 b]

    const int tid  = threadIdx.x;
    const int lane = tid & 31;
    const int wid  = tid >> 5;
    const int rg   = wid >> 2;          // row group (96 rows)
    const int kc   = wid & 3;           // k-chunk
    const int k0   = kc << 6;

    const int rank = blockIdx.x & 3;
    const int cg   = blockIdx.x >> 2;
    const int g    = cg >> 3;
    const int c    = cg & 7;
    const int l    = g >> 1;
    const int dir  = g & 1;
    const int b0   = c * 4;

    // combine identity (tid < 128)
    const int li   = tid & 63;
    const int half = (tid >> 6) & 1;    // batch pair: half*2, half*2+1
    const int hi   = rank * 64 + li;
    const int ba   = half * 2;

    const float* WhL = Wh + (size_t)l * 768 * 256;

    // 2 register rows (k0..k0+63 each)
    const int rrA = rg * 96 + lane * 3;
    float4 w0[16], w1[16];
    {
        int r0 = rrA + 0, r1 = rrA + 1;
        const float4* p0 = reinterpret_cast<const float4*>(
            WhL + (size_t)((r0 >> 6) * 256 + rank * 64 + (r0 & 63)) * 256 + k0);
        const float4* p1 = reinterpret_cast<const float4*>(
            WhL + (size_t)((r1 >> 6) * 256 + rank * 64 + (r1 & 63)) * 256 + k0);
#pragma unroll
        for (int q = 0; q < 16; q++) { w0[q] = p0[q]; w1[q] = p1[q]; }
    }

    // 3rd-row smem plane: w3[rg][k][lane]
    for (int i = tid; i < SW3_F; i += SC_THREADS) {
        int rg_ = i >> 13;
        int rem = i & 8191;
        int k   = rem >> 5;
        int ln  = rem & 31;
        int rr  = rg_ * 96 + ln * 3 + 2;
        sw3[i] = WhL[(size_t)((rr >> 6) * 256 + rank * 64 + (rr & 63)) * 256 + k];
    }
    for (int i = tid; i < HBUF_F; i += SC_THREADS) hbuf[i] = 0.f;

    float br = 0.f, bz = 0.f, bn = 0.f;
    if (tid < 128) {
        br = bh[l * 768 +       hi];
        bz = bh[l * 768 + 256 + hi];
        bn = bh[l * 768 + 512 + hi];
    }

    const uint32_t smem_u32 = (uint32_t)__cvta_generic_to_shared(sm);
    const uint32_t mb = smem_u32 + MBAR_OFF;
    if (tid == 0) mbar_init(mb, 512);   // 4 warps x 4 src-ranks x count 32

    __syncthreads();
    cluster_barrier();   // mbar + smem init visible cluster-wide

    const uint32_t hbuf_saddr = (uint32_t)__cvta_generic_to_shared(hbuf);

    float hprev0 = 0.f, hprev1 = 0.f;
    int p = 0;
    uint32_t par = 0;

    for (int step = 0; step < T_LEN; step++) {
        const int t = dir ? (T_LEN - 1 - step) : step;

        // prefetch gx for combine (6 loads; latency hidden under the dot)
        float gxr0, gxr1, gxz0, gxz1, gxn0, gxn1;
        if (tid < 128) {
            const size_t base = ((size_t)t * LAY + l) * 3 * BSZ * HID
                              + (size_t)(b0 + ba) * HID + hi;
            const size_t gsz = (size_t)BSZ * HID;
            gxr0 = __ldg(g_gx + base);
            gxr1 = __ldg(g_gx + base + HID);
            gxz0 = __ldg(g_gx + base + gsz);
            gxz1 = __ldg(g_gx + base + gsz + HID);
            gxn0 = __ldg(g_gx + base + 2 * gsz);
            gxn1 = __ldg(g_gx + base + 2 * gsz + HID);
        }

        // --- split-K dot: 3 rows x 4 batches over 64 k ---
        ull a00 = 0, a01v = 0, a10 = 0, a11v = 0, a20 = 0, a21v = 0;
        {
            const ulonglong2* hp = reinterpret_cast<const ulonglong2*>(hbuf)
                                   + p * 256 + k0;
            const float* w3p = sw3 + ((rg << 8) + k0) * 32 + lane;
            const float* f0 = reinterpret_cast<const float*>(w0);
            const float* f1 = reinterpret_cast<const float*>(w1);
#pragma unroll
            for (int kk = 0; kk < 64; kk++) {
                ulonglong2 hk = hp[kk];
                float v2 = w3p[kk << 5];
                ull s0 = splat2(f0[kk]);
                ull s1 = splat2(f1[kk]);
                ull s2 = splat2(v2);
                ffma2(a00, s0, hk.x); ffma2(a01v, s0, hk.y);
                ffma2(a10, s1, hk.x); ffma2(a11v, s1, hk.y);
                ffma2(a20, s2, hk.x); ffma2(a21v, s2, hk.y);
            }
        }
        {
            float2* pA = reinterpret_cast<float2*>(partA) + kc * 192 + rrA;
            float2* pB = reinterpret_cast<float2*>(partB) + kc * 192 + rrA;
            pA[0] = unpack2(a00); pB[0] = unpack2(a01v);
            pA[1] = unpack2(a10); pB[1] = unpack2(a11v);
            pA[2] = unpack2(a20); pB[2] = unpack2(a21v);
        }
        __syncthreads();

        // --- single-phase combine: 128 threads own (hi, batch pair) ---
        if (tid < 128) {
            const float2* pp = reinterpret_cast<const float2*>(half ? partB : partA);
            float2 q;
            float aR0, aR1, aZ0, aZ1, aN0, aN1;
            q = pp[0 * 192 + li];        aR0 = q.x;  aR1 = q.y;
            q = pp[1 * 192 + li];        aR0 += q.x; aR1 += q.y;
            q = pp[2 * 192 + li];        aR0 += q.x; aR1 += q.y;
            q = pp[3 * 192 + li];        aR0 += q.x; aR1 += q.y;
            q = pp[0 * 192 + 64 + li];   aZ0 = q.x;  aZ1 = q.y;
            q = pp[1 * 192 + 64 + li];   aZ0 += q.x; aZ1 += q.y;
            q = pp[2 * 192 + 64 + li];   aZ0 += q.x; aZ1 += q.y;
            q = pp[3 * 192 + 64 + li];   aZ0 += q.x; aZ1 += q.y;
            q = pp[0 * 192 + 128 + li];  aN0 = q.x;  aN1 = q.y;
            q = pp[1 * 192 + 128 + li];  aN0 += q.x; aN1 += q.y;
            q = pp[2 * 192 + 128 + li];  aN0 += q.x; aN1 += q.y;
            q = pp[3 * 192 + 128 + li];  aN0 += q.x; aN1 += q.y;

            const float r0 = sig_fast(gxr0 + aR0 + br);
            const float r1 = sig_fast(gxr1 + aR1 + br);
            const float z0 = sig_fast(gxz0 + aZ0 + bz);
            const float z1 = sig_fast(gxz1 + aZ1 + bz);
            const float n0 = tanh_fast(gxn0 + r0 * (aN0 + bn));
            const float n1 = tanh_fast(gxn1 + r1 * (aN1 + bn));
            const float h0 = (1.f - z0) * n0 + z0 * hprev0;
            const float h1 = (1.f - z1) * n1 + z1 * hprev1;
            hprev0 = h0; hprev1 = h1;

            const size_t obase = ((size_t)t * LAY + l) * (2 * HID) + dir * HID + hi;
            out[(size_t)(b0 + ba + 0) * ((size_t)T_LEN * LAY * 2 * HID) + obase] = h0;
            out[(size_t)(b0 + ba + 1) * ((size_t)T_LEN * LAY * 2 * HID) + obase] = h1;

            const uint32_t la = hbuf_saddr
                + (uint32_t)((((1 - p) * 256 + hi) * 4 + ba) * 4);
#pragma unroll
            for (int r2 = 0; r2 < 4; r2++) st_cluster_v2(la, r2, h0, h1);

            __syncwarp();
            if (lane == 0) {
#pragma unroll
                for (int r2 = 0; r2 < 4; r2++) mbar_arrive_remote(mb, r2, 32);
            }
        }

        mbar_wait(mb, par);
        par ^= 1;
        p   ^= 1;
    }
    cluster_barrier();
}

// ---------------------------------------------------------------------------
extern "C" void kernel_launch(void* const* d_in, const int* in_sizes, int n_in,
                              void* d_out, int out_size)
{
    (void)in_sizes; (void)n_in; (void)out_size;
    const float* x  = (const float*)d_in[0];
    const float* Wx = (const float*)d_in[1];
    const float* Wh = (const float*)d_in[2];
    const float* bx = (const float*)d_in[3];
    const float* bh = (const float*)d_in[4];
    float* out = (float*)d_out;

    const int smem1 = (128 + 64) * APAD * 4;   // 199,680 B
    const int smem2 = MBAR_OFF + 16;           //  86,032 B

    cudaFuncSetAttribute(gx_gemm_kernel, cudaFuncAttributeMaxDynamicSharedMemorySize, smem1);
    cudaFuncSetAttribute(gru_scan_kernel, cudaFuncAttributeMaxDynamicSharedMemorySize, smem2);

    dim3 grid1(1536 / 64, 128);   // 24 x 128 CTAs, each does 4 x 128-row m-tiles
    gx_gemm_kernel<<<grid1, 256, smem1>>>(x, Wx, bx);

    gru_scan_kernel<<<128, SC_THREADS, smem2>>>(Wh, bh, out);
}

// round 6
// speedup vs baseline: 1.0669x; 1.0669x over previous
#include <cuda_runtime.h>
#include <cstdint>
#include <math.h>

#define T_LEN 2048
#define BSZ   32
#define DIM   256
#define HID   256
#define LAY   2

typedef unsigned long long ull;

// Scratch: gx[t][l][gate3][b][h]  (2048*2*3*32*256 floats = 402MB)
__device__ float g_gx[(size_t)T_LEN * LAY * 3 * BSZ * HID];

__device__ __forceinline__ void ffma2(ull& d, ull a, ull b) {
    asm("fma.rn.f32x2 %0, %1, %2, %0;" : "+l"(d) : "l"(a), "l"(b));
}
__device__ __forceinline__ float2 unpack2(ull v) {
    float2 r; asm("mov.b64 {%0, %1}, %2;" : "=f"(r.x), "=f"(r.y) : "l"(v)); return r;
}
__device__ __forceinline__ float hsum2(ull v) {
    float2 r = unpack2(v); return r.x + r.y;
}

// ---------------------------------------------------------------------------
// Kernel 1: gx GEMM. 128m x 64n block, 8m x 4n thread tile, full K in smem.
// ---------------------------------------------------------------------------
#define APAD 260

__global__ __launch_bounds__(256, 1)
void gx_gemm_kernel(const float* __restrict__ x, const float* __restrict__ Wx,
                    const float* __restrict__ bx)
{
    extern __shared__ float sm1[];
    float* sA = sm1;               // [128][APAD]
    float* sB = sm1 + 128 * APAD;  // [64][APAD]

    const int tid = threadIdx.x;
    const int tx  = tid & 15;
    const int ty  = tid >> 4;
    const int nbase = blockIdx.x * 64;

    for (int idx = tid; idx < 64 * 64; idx += 256) {
        int j = idx >> 6, k4 = idx & 63;
        float4 v = *reinterpret_cast<const float4*>(
            Wx + (((size_t)(nbase + j)) << 8) + (k4 << 2));
        *reinterpret_cast<float4*>(sB + j * APAD + (k4 << 2)) = v;
    }

    int   ncol[4];
    float bias[4];
#pragma unroll
    for (int jj = 0; jj < 4; jj++) {
        ncol[jj] = nbase + tx + 16 * jj;
        bias[jj] = bx[ncol[jj]];
    }
    __syncthreads();

    for (int ms = 0; ms < 4; ms++) {
        const int mbase = (blockIdx.y * 4 + ms) * 128;
        for (int idx = tid; idx < 128 * 64; idx += 256) {
            int r = idx >> 6, k4 = idx & 63;
            float4 v = *reinterpret_cast<const float4*>(
                x + (((size_t)(mbase + r)) << 8) + (k4 << 2));
            *reinterpret_cast<float4*>(sA + r * APAD + (k4 << 2)) = v;
        }
        __syncthreads();

        ull acc2[8][4];
#pragma unroll
        for (int i = 0; i < 8; i++)
#pragma unroll
            for (int j = 0; j < 4; j++) acc2[i][j] = 0ull;

#pragma unroll 2
        for (int k4 = 0; k4 < 64; k4++) {
            ulonglong2 av[8], bv[4];
#pragma unroll
            for (int ii = 0; ii < 8; ii++)
                av[ii] = *reinterpret_cast<const ulonglong2*>(sA + (ty * 8 + ii) * APAD + (k4 << 2));
#pragma unroll
            for (int jj = 0; jj < 4; jj++)
                bv[jj] = *reinterpret_cast<const ulonglong2*>(sB + (tx + 16 * jj) * APAD + (k4 << 2));
#pragma unroll
            for (int ii = 0; ii < 8; ii++)
#pragma unroll
                for (int jj = 0; jj < 4; jj++) {
                    ffma2(acc2[ii][jj], av[ii].x, bv[jj].x);
                    ffma2(acc2[ii][jj], av[ii].y, bv[jj].y);
                }
        }

#pragma unroll
        for (int jj = 0; jj < 4; jj++) {
            const int n  = ncol[jj];
            const int l  = n / 768;
            const int rr = n - l * 768;
            const int g3 = rr >> 8;
            const int h  = rr & 255;
#pragma unroll
            for (int ii = 0; ii < 8; ii++) {
                const int m = mbase + ty * 8 + ii;
                const int b = m >> 11;
                const int t = m & 2047;
                const size_t o =
                    ((((size_t)t * LAY + l) * 3 + g3) * BSZ + b) * HID + h;
                g_gx[o] = hsum2(acc2[ii][jj]) + bias[jj];
            }
        }
        __syncthreads();
    }
}

// ---------------------------------------------------------------------------
// Kernel 2: cluster-persistent GRU scan, k-pair-packed f32x2 (mov-free dot).
// 128 CTAs = 4 groups x 8 batch-chunks x 4-CTA cluster. 256 threads.
// Warp (rg,kc): rows rg*96 + lane*3 + {0,1,2}, k-chunk kc*64..+63.
// hbuf layout [p][b][k] -> k-contiguous: LDS.128 broadcast gives packed k-pairs.
// Rows 0,1 in regs as packed k-pairs (zero movs); row 2 in smem [lane][k].
// Sync: split barrier.cluster arrive/wait (wait hidden under gx prefetch).
// ---------------------------------------------------------------------------
#define SC_THREADS 256
#define PADK    260                              // w3 row stride (mult of 4)
#define SW3_F   (2 * 32 * PADK)                  // 16640 floats
#define PART_F  (4 * 192 * 2)                    //  1536 floats per half-plane
#define HBUF_F  (2 * 4 * 256)                    //  2048 floats

__device__ __forceinline__ void st_cluster_f32(uint32_t saddr, int trank, float v)
{
    uint32_t ra;
    asm volatile("mapa.shared::cluster.u32 %0, %1, %2;" : "=r"(ra) : "r"(saddr), "r"(trank));
    asm volatile("st.shared::cluster.f32 [%0], %1;" :: "r"(ra), "f"(v) : "memory");
}
__device__ __forceinline__ void cluster_arrive()
{ asm volatile("barrier.cluster.arrive.aligned;" ::: "memory"); }
__device__ __forceinline__ void cluster_wait()
{ asm volatile("barrier.cluster.wait.aligned;" ::: "memory"); }
__device__ __forceinline__ float sig_fast(float x) {
    return __fdividef(1.f, 1.f + __expf(-x));
}
__device__ __forceinline__ float tanh_fast(float x) {
    x = fminf(fmaxf(x, -15.f), 15.f);
    float e = __expf(2.f * x);
    return __fdividef(e - 1.f, e + 1.f);
}

__global__ void __cluster_dims__(4, 1, 1) __launch_bounds__(SC_THREADS, 1)
gru_scan_kernel(const float* __restrict__ Wh, const float* __restrict__ bh,
                float* __restrict__ out)
{
    extern __shared__ float sm[];
    float* sw3   = sm;                  // [2 rg * 32 lane][PADK]
    float* partA = sw3 + SW3_F;         // [4 kc][192 rr] float2 (b0,b1)
    float* partB = partA + PART_F;      // [4 kc][192 rr] float2 (b2,b3)
    float* hbuf  = partB + PART_F;      // [2 p][4 b][256 k]

    const int tid  = threadIdx.x;
    const int lane = tid & 31;
    const int wid  = tid >> 5;
    const int rg   = wid >> 2;          // row group (96 rows)
    const int kc   = wid & 3;           // k-chunk
    const int k0   = kc << 6;

    const int rank = blockIdx.x & 3;
    const int cg   = blockIdx.x >> 2;
    const int g    = cg >> 3;
    const int c    = cg & 7;
    const int l    = g >> 1;
    const int dir  = g & 1;
    const int b0   = c * 4;

    // combine identity (tid < 128)
    const int li   = tid & 63;
    const int half = (tid >> 6) & 1;
    const int hi   = rank * 64 + li;
    const int ba   = half * 2;

    const float* WhL = Wh + (size_t)l * 768 * 256;

    // 2 register rows, stored as packed k-pairs (32 ull each)
    const int rrA = rg * 96 + lane * 3;
    ull w0r[32], w1r[32];
    {
        int r0 = rrA + 0, r1 = rrA + 1;
        const ull* p0 = reinterpret_cast<const ull*>(
            WhL + (size_t)((r0 >> 6) * 256 + rank * 64 + (r0 & 63)) * 256 + k0);
        const ull* p1 = reinterpret_cast<const ull*>(
            WhL + (size_t)((r1 >> 6) * 256 + rank * 64 + (r1 & 63)) * 256 + k0);
#pragma unroll
        for (int q = 0; q < 32; q++) { w0r[q] = p0[q]; w1r[q] = p1[q]; }
    }

    // 3rd-row smem plane: sw3[(rg*32+lane)][k]
    for (int i = tid; i < 2 * 32 * 256; i += SC_THREADS) {
        int ri = i >> 8;                // 0..63  (rg*32+ln)
        int k  = i & 255;
        int rg_ = ri >> 5;
        int ln  = ri & 31;
        int rr  = rg_ * 96 + ln * 3 + 2;
        sw3[ri * PADK + k] = WhL[(size_t)((rr >> 6) * 256 + rank * 64 + (rr & 63)) * 256 + k];
    }
    for (int i = tid; i < HBUF_F; i += SC_THREADS) hbuf[i] = 0.f;

    float br = 0.f, bz = 0.f, bn = 0.f;
    if (tid < 128) {
        br = bh[l * 768 +       hi];
        bz = bh[l * 768 + 256 + hi];
        bn = bh[l * 768 + 512 + hi];
    }

    __syncthreads();
    cluster_arrive(); cluster_wait();   // init visible cluster-wide
    cluster_arrive();                   // pre-arm phase for iter-0 wait

    const uint32_t hbuf_saddr = (uint32_t)__cvta_generic_to_shared(hbuf);

    float hprev0 = 0.f, hprev1 = 0.f;
    int p = 0;

    for (int step = 0; step < T_LEN; step++) {
        const int t = dir ? (T_LEN - 1 - step) : step;

        // gx prefetch (in flight while we wait on the cluster barrier)
        float gxr0, gxr1, gxz0, gxz1, gxn0, gxn1;
        if (tid < 128) {
            const size_t base = ((size_t)t * LAY + l) * 3 * BSZ * HID
                              + (size_t)(b0 + ba) * HID + hi;
            const size_t gsz = (size_t)BSZ * HID;
            gxr0 = __ldg(g_gx + base);
            gxr1 = __ldg(g_gx + base + HID);
            gxz0 = __ldg(g_gx + base + gsz);
            gxz1 = __ldg(g_gx + base + gsz + HID);
            gxn0 = __ldg(g_gx + base + 2 * gsz);
            gxn1 = __ldg(g_gx + base + 2 * gsz + HID);
        }

        cluster_wait();   // h(step-1) visible everywhere

        // --- dot: 3 rows x 4 batches over 64 k, k-pair packed, mov-free ---
        ull acc[3][4];
#pragma unroll
        for (int r = 0; r < 3; r++)
#pragma unroll
            for (int b = 0; b < 4; b++) acc[r][b] = 0ull;
        {
            const ulonglong2* hB[4];
#pragma unroll
            for (int b = 0; b < 4; b++)
                hB[b] = reinterpret_cast<const ulonglong2*>(hbuf + ((p * 4 + b) << 8) + k0);
            const ulonglong2* w3p = reinterpret_cast<const ulonglong2*>(
                sw3 + (rg * 32 + lane) * PADK + k0);

#pragma unroll 8
            for (int q = 0; q < 16; q++) {       // 2 k-pairs per iter
                ulonglong2 w3 = w3p[q];          // row2, k-pairs 2q,2q+1
                ulonglong2 h0 = hB[0][q];
                ulonglong2 h1 = hB[1][q];
                ulonglong2 h2 = hB[2][q];
                ulonglong2 h3 = hB[3][q];
                ull wa0 = w0r[2 * q], wa1 = w0r[2 * q + 1];
                ull wb0 = w1r[2 * q], wb1 = w1r[2 * q + 1];
                ffma2(acc[0][0], wa0, h0.x); ffma2(acc[0][0], wa1, h0.y);
                ffma2(acc[0][1], wa0, h1.x); ffma2(acc[0][1], wa1, h1.y);
                ffma2(acc[0][2], wa0, h2.x); ffma2(acc[0][2], wa1, h2.y);
                ffma2(acc[0][3], wa0, h3.x); ffma2(acc[0][3], wa1, h3.y);
                ffma2(acc[1][0], wb0, h0.x); ffma2(acc[1][0], wb1, h0.y);
                ffma2(acc[1][1], wb0, h1.x); ffma2(acc[1][1], wb1, h1.y);
                ffma2(acc[1][2], wb0, h2.x); ffma2(acc[1][2], wb1, h2.y);
                ffma2(acc[1][3], wb0, h3.x); ffma2(acc[1][3], wb1, h3.y);
                ffma2(acc[2][0], w3.x, h0.x); ffma2(acc[2][0], w3.y, h0.y);
                ffma2(acc[2][1], w3.x, h1.x); ffma2(acc[2][1], w3.y, h1.y);
                ffma2(acc[2][2], w3.x, h2.x); ffma2(acc[2][2], w3.y, h2.y);
                ffma2(acc[2][3], w3.x, h3.x); ffma2(acc[2][3], w3.y, h3.y);
            }
        }
        {
            float2* pA = reinterpret_cast<float2*>(partA) + kc * 192 + rrA;
            float2* pB = reinterpret_cast<float2*>(partB) + kc * 192 + rrA;
#pragma unroll
            for (int r = 0; r < 3; r++) {
                pA[r] = make_float2(hsum2(acc[r][0]), hsum2(acc[r][1]));
                pB[r] = make_float2(hsum2(acc[r][2]), hsum2(acc[r][3]));
            }
        }
        __syncthreads();

        // --- single-phase combine: 128 threads own (hi, batch pair) ---
        if (tid < 128) {
            const float2* pp = reinterpret_cast<const float2*>(half ? partB : partA);
            float aR0, aR1, aZ0, aZ1, aN0, aN1;
            {
                float2 q0 = pp[0 * 192 + li],       q1 = pp[1 * 192 + li];
                float2 q2 = pp[2 * 192 + li],       q3 = pp[3 * 192 + li];
                aR0 = (q0.x + q1.x) + (q2.x + q3.x);
                aR1 = (q0.y + q1.y) + (q2.y + q3.y);
            }
            {
                float2 q0 = pp[0 * 192 + 64 + li],  q1 = pp[1 * 192 + 64 + li];
                float2 q2 = pp[2 * 192 + 64 + li],  q3 = pp[3 * 192 + 64 + li];
                aZ0 = (q0.x + q1.x) + (q2.x + q3.x);
                aZ1 = (q0.y + q1.y) + (q2.y + q3.y);
            }
            {
                float2 q0 = pp[0 * 192 + 128 + li], q1 = pp[1 * 192 + 128 + li];
                float2 q2 = pp[2 * 192 + 128 + li], q3 = pp[3 * 192 + 128 + li];
                aN0 = (q0.x + q1.x) + (q2.x + q3.x);
                aN1 = (q0.y + q1.y) + (q2.y + q3.y);
            }

            const float r0 = sig_fast(gxr0 + aR0 + br);
            const float r1 = sig_fast(gxr1 + aR1 + br);
            const float z0 = sig_fast(gxz0 + aZ0 + bz);
            const float z1 = sig_fast(gxz1 + aZ1 + bz);
            const float n0 = tanh_fast(gxn0 + r0 * (aN0 + bn));
            const float n1 = tanh_fast(gxn1 + r1 * (aN1 + bn));
            const float h0 = (1.f - z0) * n0 + z0 * hprev0;
            const float h1 = (1.f - z1) * n1 + z1 * hprev1;
            hprev0 = h0; hprev1 = h1;

            const size_t obase = ((size_t)t * LAY + l) * (2 * HID) + dir * HID + hi;
            out[(size_t)(b0 + ba + 0) * ((size_t)T_LEN * LAY * 2 * HID) + obase] = h0;
            out[(size_t)(b0 + ba + 1) * ((size_t)T_LEN * LAY * 2 * HID) + obase] = h1;

            // broadcast h_new into all 4 ranks' hbuf[1-p][ba..ba+1][hi]
            const uint32_t la0 = hbuf_saddr
                + (uint32_t)(((((1 - p) * 4 + ba) << 8) + hi) * 4);
            const uint32_t la1 = la0 + 1024;
#pragma unroll
            for (int r2 = 0; r2 < 4; r2++) {
                st_cluster_f32(la0, r2, h0);
                st_cluster_f32(la1, r2, h1);
            }
        }

        cluster_arrive();   // release h stores; also fences part reuse
        p ^= 1;
    }
    cluster_wait();
}

// ---------------------------------------------------------------------------
extern "C" void kernel_launch(void* const* d_in, const int* in_sizes, int n_in,
                              void* d_out, int out_size)
{
    (void)in_sizes; (void)n_in; (void)out_size;
    const float* x  = (const float*)d_in[0];
    const float* Wx = (const float*)d_in[1];
    const float* Wh = (const float*)d_in[2];
    const float* bx = (const float*)d_in[3];
    const float* bh = (const float*)d_in[4];
    float* out = (float*)d_out;

    const int smem1 = (128 + 64) * APAD * 4;                       // 199,680 B
    const int smem2 = (SW3_F + 2 * PART_F + HBUF_F) * 4;           //  87,296 B

    cudaFuncSetAttribute(gx_gemm_kernel, cudaFuncAttributeMaxDynamicSharedMemorySize, smem1);
    cudaFuncSetAttribute(gru_scan_kernel, cudaFuncAttributeMaxDynamicSharedMemorySize, smem2);

    dim3 grid1(1536 / 64, 128);
    gx_gemm_kernel<<<grid1, 256, smem1>>>(x, Wx, bx);

    gru_scan_kernel<<<128, SC_THREADS, smem2>>>(Wh, bh, out);
}

// round 7
// speedup vs baseline: 1.1132x; 1.0433x over previous
#include <cuda_runtime.h>
#include <cstdint>
#include <math.h>

#define T_LEN 2048
#define BSZ   32
#define DIM   256
#define HID   256
#define LAY   2

typedef unsigned long long ull;

// Scratch: gx[t][l][gate3][b][h]  (2048*2*3*32*256 floats = 402MB)
__device__ float g_gx[(size_t)T_LEN * LAY * 3 * BSZ * HID];

__device__ __forceinline__ void ffma2(ull& d, ull a, ull b) {
    asm("fma.rn.f32x2 %0, %1, %2, %0;" : "+l"(d) : "l"(a), "l"(b));
}
__device__ __forceinline__ float2 unpack2(ull v) {
    float2 r; asm("mov.b64 {%0, %1}, %2;" : "=f"(r.x), "=f"(r.y) : "l"(v)); return r;
}
__device__ __forceinline__ float hsum2(ull v) {
    float2 r = unpack2(v); return r.x + r.y;
}

// ---------------------------------------------------------------------------
// Kernel 1: gx GEMM. 128m x 64n block, 8m x 4n thread tile, full K in smem.
// ---------------------------------------------------------------------------
#define APAD 260

__global__ __launch_bounds__(256, 1)
void gx_gemm_kernel(const float* __restrict__ x, const float* __restrict__ Wx,
                    const float* __restrict__ bx)
{
    extern __shared__ float sm1[];
    float* sA = sm1;               // [128][APAD]
    float* sB = sm1 + 128 * APAD;  // [64][APAD]

    const int tid = threadIdx.x;
    const int tx  = tid & 15;
    const int ty  = tid >> 4;
    const int nbase = blockIdx.x * 64;

    for (int idx = tid; idx < 64 * 64; idx += 256) {
        int j = idx >> 6, k4 = idx & 63;
        float4 v = *reinterpret_cast<const float4*>(
            Wx + (((size_t)(nbase + j)) << 8) + (k4 << 2));
        *reinterpret_cast<float4*>(sB + j * APAD + (k4 << 2)) = v;
    }

    int   ncol[4];
    float bias[4];
#pragma unroll
    for (int jj = 0; jj < 4; jj++) {
        ncol[jj] = nbase + tx + 16 * jj;
        bias[jj] = bx[ncol[jj]];
    }
    __syncthreads();

    for (int ms = 0; ms < 4; ms++) {
        const int mbase = (blockIdx.y * 4 + ms) * 128;
        for (int idx = tid; idx < 128 * 64; idx += 256) {
            int r = idx >> 6, k4 = idx & 63;
            float4 v = *reinterpret_cast<const float4*>(
                x + (((size_t)(mbase + r)) << 8) + (k4 << 2));
            *reinterpret_cast<float4*>(sA + r * APAD + (k4 << 2)) = v;
        }
        __syncthreads();

        ull acc2[8][4];
#pragma unroll
        for (int i = 0; i < 8; i++)
#pragma unroll
            for (int j = 0; j < 4; j++) acc2[i][j] = 0ull;

#pragma unroll 2
        for (int k4 = 0; k4 < 64; k4++) {
            ulonglong2 av[8], bv[4];
#pragma unroll
            for (int ii = 0; ii < 8; ii++)
                av[ii] = *reinterpret_cast<const ulonglong2*>(sA + (ty * 8 + ii) * APAD + (k4 << 2));
#pragma unroll
            for (int jj = 0; jj < 4; jj++)
                bv[jj] = *reinterpret_cast<const ulonglong2*>(sB + (tx + 16 * jj) * APAD + (k4 << 2));
#pragma unroll
            for (int ii = 0; ii < 8; ii++)
#pragma unroll
                for (int jj = 0; jj < 4; jj++) {
                    ffma2(acc2[ii][jj], av[ii].x, bv[jj].x);
                    ffma2(acc2[ii][jj], av[ii].y, bv[jj].y);
                }
        }

#pragma unroll
        for (int jj = 0; jj < 4; jj++) {
            const int n  = ncol[jj];
            const int l  = n / 768;
            const int rr = n - l * 768;
            const int g3 = rr >> 8;
            const int h  = rr & 255;
#pragma unroll
            for (int ii = 0; ii < 8; ii++) {
                const int m = mbase + ty * 8 + ii;
                const int b = m >> 11;
                const int t = m & 2047;
                const size_t o =
                    ((((size_t)t * LAY + l) * 3 + g3) * BSZ + b) * HID + h;
                g_gx[o] = hsum2(acc2[ii][jj]) + bias[jj];
            }
        }
        __syncthreads();
    }
}

// ---------------------------------------------------------------------------
// Kernel 2: cluster-persistent GRU scan, k-pair-packed mov-free dot,
// FULLY-UNROLLED so weight arrays stay in registers.
// 128 CTAs = 4 groups x 8 batch-chunks x 4-CTA cluster. 256 threads.
// Dot warps (rg,kc): rows rg*96 + lane*3 + {0,1,2}, k-chunk kc*64..+63.
// Combine: 256 threads, each owns (h=rank*64+li, batch b=tid>>6).
// ---------------------------------------------------------------------------
#define SC_THREADS 256
#define PADK    260
#define SW3_F   (2 * 32 * PADK)                  // 16640 floats
#define PART_F  (4 * 192 * 2)                    //  1536 floats per half-plane
#define HBUF_F  (2 * 4 * 256)                    //  2048 floats

__device__ __forceinline__ void st_cluster_f32(uint32_t saddr, int trank, float v)
{
    uint32_t ra;
    asm volatile("mapa.shared::cluster.u32 %0, %1, %2;" : "=r"(ra) : "r"(saddr), "r"(trank));
    asm volatile("st.shared::cluster.f32 [%0], %1;" :: "r"(ra), "f"(v) : "memory");
}
__device__ __forceinline__ void cluster_arrive()
{ asm volatile("barrier.cluster.arrive.aligned;" ::: "memory"); }
__device__ __forceinline__ void cluster_wait()
{ asm volatile("barrier.cluster.wait.aligned;" ::: "memory"); }
__device__ __forceinline__ float sig_fast(float x) {
    return __fdividef(1.f, 1.f + __expf(-x));
}
__device__ __forceinline__ float tanh_fast(float x) {
    x = fminf(fmaxf(x, -15.f), 15.f);
    float e = __expf(2.f * x);
    return __fdividef(e - 1.f, e + 1.f);
}

__global__ void __cluster_dims__(4, 1, 1) __launch_bounds__(SC_THREADS, 1)
gru_scan_kernel(const float* __restrict__ Wh, const float* __restrict__ bh,
                float* __restrict__ out)
{
    extern __shared__ float sm[];
    float* sw3   = sm;                  // [64 rows][PADK]  (row2 weights)
    float* partA = sw3 + SW3_F;         // [4 kc][192 rr] float2 (b0,b1)
    float* partB = partA + PART_F;      // [4 kc][192 rr] float2 (b2,b3)
    float* hbuf  = partB + PART_F;      // [2 p][4 b][256 k]

    const int tid  = threadIdx.x;
    const int lane = tid & 31;
    const int wid  = tid >> 5;
    const int rg   = wid >> 2;          // row group (96 rows)
    const int kc   = wid & 3;           // k-chunk
    const int k0   = kc << 6;

    const int rank = blockIdx.x & 3;
    const int cg   = blockIdx.x >> 2;
    const int g    = cg >> 3;
    const int c    = cg & 7;
    const int l    = g >> 1;
    const int dir  = g & 1;
    const int b0   = c * 4;

    // combine identity: all 256 threads, each (hi, one batch)
    const int li = tid & 63;
    const int bb = tid >> 6;            // 0..3
    const int hi = rank * 64 + li;

    const float* WhL = Wh + (size_t)l * 768 * 256;

    // 2 register rows as packed k-pairs (32 ull each; static indexing only)
    const int rrA = rg * 96 + lane * 3;
    ull w0r[32], w1r[32];
    {
        int r0 = rrA + 0, r1 = rrA + 1;
        const ull* p0 = reinterpret_cast<const ull*>(
            WhL + (size_t)((r0 >> 6) * 256 + rank * 64 + (r0 & 63)) * 256 + k0);
        const ull* p1 = reinterpret_cast<const ull*>(
            WhL + (size_t)((r1 >> 6) * 256 + rank * 64 + (r1 & 63)) * 256 + k0);
#pragma unroll
        for (int q = 0; q < 32; q++) { w0r[q] = p0[q]; w1r[q] = p1[q]; }
    }

    // 3rd-row smem plane: sw3[(rg*32+lane)][k]
    for (int i = tid; i < 2 * 32 * 256; i += SC_THREADS) {
        int ri = i >> 8;
        int k  = i & 255;
        int rg_ = ri >> 5;
        int ln  = ri & 31;
        int rr  = rg_ * 96 + ln * 3 + 2;
        sw3[ri * PADK + k] = WhL[(size_t)((rr >> 6) * 256 + rank * 64 + (rr & 63)) * 256 + k];
    }
    for (int i = tid; i < HBUF_F; i += SC_THREADS) hbuf[i] = 0.f;

    const float br = bh[l * 768 +       hi];
    const float bz = bh[l * 768 + 256 + hi];
    const float bn = bh[l * 768 + 512 + hi];

    __syncthreads();
    cluster_arrive(); cluster_wait();   // init visible cluster-wide
    cluster_arrive();                   // pre-arm phase for iter-0 wait

    const uint32_t hbuf_saddr = (uint32_t)__cvta_generic_to_shared(hbuf);
    const size_t gsz = (size_t)BSZ * HID;

    float hprev = 0.f;
    int p = 0;

    for (int step = 0; step < T_LEN; step++) {
        const int t = dir ? (T_LEN - 1 - step) : step;

        // gx prefetch (in flight while waiting on the cluster barrier)
        float gxr, gxz, gxn;
        {
            const size_t base = ((size_t)t * LAY + l) * 3 * BSZ * HID
                              + (size_t)(b0 + bb) * HID + hi;
            gxr = __ldg(g_gx + base);
            gxz = __ldg(g_gx + base + gsz);
            gxn = __ldg(g_gx + base + 2 * gsz);
        }

        cluster_wait();   // h(step-1) visible everywhere

        // --- dot: 3 rows x 4 batches over 64 k, k-pair packed, mov-free ---
        ull a00 = 0, a01 = 0, a02 = 0, a03 = 0;
        ull a10 = 0, a11 = 0, a12 = 0, a13 = 0;
        ull a20 = 0, a21 = 0, a22 = 0, a23 = 0;
        {
            const ulonglong2* h0p = reinterpret_cast<const ulonglong2*>(hbuf + ((p * 4 + 0) << 8) + k0);
            const ulonglong2* h1p = reinterpret_cast<const ulonglong2*>(hbuf + ((p * 4 + 1) << 8) + k0);
            const ulonglong2* h2p = reinterpret_cast<const ulonglong2*>(hbuf + ((p * 4 + 2) << 8) + k0);
            const ulonglong2* h3p = reinterpret_cast<const ulonglong2*>(hbuf + ((p * 4 + 3) << 8) + k0);
            const ulonglong2* w3p = reinterpret_cast<const ulonglong2*>(
                sw3 + (rg * 32 + lane) * PADK + k0);

#pragma unroll
            for (int q = 0; q < 16; q++) {      // FULL unroll: static reg indices
                const ulonglong2 w3 = w3p[q];
                const ulonglong2 hh0 = h0p[q];
                const ulonglong2 hh1 = h1p[q];
                const ulonglong2 hh2 = h2p[q];
                const ulonglong2 hh3 = h3p[q];
                const ull wa0 = w0r[2 * q], wa1 = w0r[2 * q + 1];
                const ull wb0 = w1r[2 * q], wb1 = w1r[2 * q + 1];
                ffma2(a00, wa0, hh0.x); ffma2(a00, wa1, hh0.y);
                ffma2(a01, wa0, hh1.x); ffma2(a01, wa1, hh1.y);
                ffma2(a02, wa0, hh2.x); ffma2(a02, wa1, hh2.y);
                ffma2(a03, wa0, hh3.x); ffma2(a03, wa1, hh3.y);
                ffma2(a10, wb0, hh0.x); ffma2(a10, wb1, hh0.y);
                ffma2(a11, wb0, hh1.x); ffma2(a11, wb1, hh1.y);
                ffma2(a12, wb0, hh2.x); ffma2(a12, wb1, hh2.y);
                ffma2(a13, wb0, hh3.x); ffma2(a13, wb1, hh3.y);
                ffma2(a20, w3.x, hh0.x); ffma2(a20, w3.y, hh0.y);
                ffma2(a21, w3.x, hh1.x); ffma2(a21, w3.y, hh1.y);
                ffma2(a22, w3.x, hh2.x); ffma2(a22, w3.y, hh2.y);
                ffma2(a23, w3.x, hh3.x); ffma2(a23, w3.y, hh3.y);
            }
        }
        {
            float2* pA = reinterpret_cast<float2*>(partA) + kc * 192 + rrA;
            float2* pB = reinterpret_cast<float2*>(partB) + kc * 192 + rrA;
            pA[0] = make_float2(hsum2(a00), hsum2(a01));
            pB[0] = make_float2(hsum2(a02), hsum2(a03));
            pA[1] = make_float2(hsum2(a10), hsum2(a11));
            pB[1] = make_float2(hsum2(a12), hsum2(a13));
            pA[2] = make_float2(hsum2(a20), hsum2(a21));
            pB[2] = make_float2(hsum2(a22), hsum2(a23));
        }
        __syncthreads();

        // --- combine: 256 threads, each owns (hi, batch bb) ---
        {
            const float* pl = (bb < 2) ? partA : partB;
            const int comp = bb & 1;
            const int base0 = (0 * 192 + li) * 2 + comp;
            const int base1 = (1 * 192 + li) * 2 + comp;
            const int base2 = (2 * 192 + li) * 2 + comp;
            const int base3 = (3 * 192 + li) * 2 + comp;
            const float aR = (pl[base0] + pl[base1]) + (pl[base2] + pl[base3]);
            const float aZ = (pl[base0 + 128] + pl[base1 + 128])
                           + (pl[base2 + 128] + pl[base3 + 128]);
            const float aN = (pl[base0 + 256] + pl[base1 + 256])
                           + (pl[base2 + 256] + pl[base3 + 256]);

            const float r = sig_fast(gxr + aR + br);
            const float z = sig_fast(gxz + aZ + bz);
            const float n = tanh_fast(gxn + r * (aN + bn));
            const float h = (1.f - z) * n + z * hprev;
            hprev = h;

            out[(size_t)(b0 + bb) * ((size_t)T_LEN * LAY * 2 * HID)
                + ((size_t)t * LAY + l) * (2 * HID) + dir * HID + hi] = h;

            // broadcast h_new into all 4 ranks' hbuf[1-p][bb][hi]
            const uint32_t la = hbuf_saddr
                + (uint32_t)(((((1 - p) * 4 + bb) << 8) + hi) * 4);
            st_cluster_f32(la, 0, h);
            st_cluster_f32(la, 1, h);
            st_cluster_f32(la, 2, h);
            st_cluster_f32(la, 3, h);
        }

        cluster_arrive();   // release h stores; fences part reuse
        p ^= 1;
    }
    cluster_wait();
}

// ---------------------------------------------------------------------------
extern "C" void kernel_launch(void* const* d_in, const int* in_sizes, int n_in,
                              void* d_out, int out_size)
{
    (void)in_sizes; (void)n_in; (void)out_size;
    const float* x  = (const float*)d_in[0];
    const float* Wx = (const float*)d_in[1];
    const float* Wh = (const float*)d_in[2];
    const float* bx = (const float*)d_in[3];
    const float* bh = (const float*)d_in[4];
    float* out = (float*)d_out;

    const int smem1 = (128 + 64) * APAD * 4;                       // 199,680 B
    const int smem2 = (SW3_F + 2 * PART_F + HBUF_F) * 4;           //  87,040 B

    cudaFuncSetAttribute(gx_gemm_kernel, cudaFuncAttributeMaxDynamicSharedMemorySize, smem1);
    cudaFuncSetAttribute(gru_scan_kernel, cudaFuncAttributeMaxDynamicSharedMemorySize, smem2);

    dim3 grid1(1536 / 64, 128);
    gx_gemm_kernel<<<grid1, 256, smem1>>>(x, Wx, bx);

    gru_scan_kernel<<<128, SC_THREADS, smem2>>>(Wh, bh, out);
}

// round 8
// speedup vs baseline: 1.3944x; 1.2527x over previous
#include <cuda_runtime.h>
#include <cstdint>
#include <math.h>

#define T_LEN 2048
#define BSZ   32
#define DIM   256
#define HID   256
#define LAY   2

typedef unsigned long long ull;

// Scratch: gx[t][l][gate3][b][h]  (2048*2*3*32*256 floats = 402MB)
__device__ float g_gx[(size_t)T_LEN * LAY * 3 * BSZ * HID];

__device__ __forceinline__ void ffma2(ull& d, ull a, ull b) {
    asm("fma.rn.f32x2 %0, %1, %2, %0;" : "+l"(d) : "l"(a), "l"(b));
}
__device__ __forceinline__ float2 unpack2(ull v) {
    float2 r; asm("mov.b64 {%0, %1}, %2;" : "=f"(r.x), "=f"(r.y) : "l"(v)); return r;
}
__device__ __forceinline__ float hsum2(ull v) {
    float2 r = unpack2(v); return r.x + r.y;
}

// ---------------------------------------------------------------------------
// Kernel 1: gx GEMM. 128m x 128n CTA tile, 8m x 8n thread tile, K chunks of 64.
//   C[m][n] = sum_k x[m][k]*Wx[n][k] + bx[n]; scatter into g_gx[t][l][g3][b][h]
// ---------------------------------------------------------------------------
#define GPAD 68    // floats per smem row (64 data + 4 pad), 16B aligned

__global__ __launch_bounds__(256, 1)
void gx_gemm_kernel(const float* __restrict__ x, const float* __restrict__ Wx,
                    const float* __restrict__ bx)
{
    extern __shared__ float sm1[];
    float* sA = sm1;                // [128][GPAD]
    float* sB = sm1 + 128 * GPAD;   // [128][GPAD]

    const int tid = threadIdx.x;
    const int tx  = tid & 15;       // n group (stride-16 cols)
    const int ty  = tid >> 4;       // m group (8 rows)
    const int nbase = blockIdx.x * 128;
    const int mbase = blockIdx.y * 128;

    int   ncol[8];
    float bias[8];
#pragma unroll
    for (int jj = 0; jj < 8; jj++) {
        ncol[jj] = nbase + tx + 16 * jj;
        bias[jj] = bx[ncol[jj]];
    }

    ull acc2[8][8];
#pragma unroll
    for (int i = 0; i < 8; i++)
#pragma unroll
        for (int j = 0; j < 8; j++) acc2[i][j] = 0ull;

    for (int kc = 0; kc < 4; kc++) {
        const int kofs = kc * 64;
        // load A and B chunks: 128 rows x 16 float4 each
        for (int idx = tid; idx < 128 * 16; idx += 256) {
            int r = idx >> 4, q = idx & 15;
            *reinterpret_cast<float4*>(sA + r * GPAD + (q << 2)) =
                *reinterpret_cast<const float4*>(x + (((size_t)(mbase + r)) << 8) + kofs + (q << 2));
            *reinterpret_cast<float4*>(sB + r * GPAD + (q << 2)) =
                *reinterpret_cast<const float4*>(Wx + (((size_t)(nbase + r)) << 8) + kofs + (q << 2));
        }
        __syncthreads();

#pragma unroll 2
        for (int q = 0; q < 16; q++) {     // 16 x (4 k) = 64 k
            ulonglong2 av[8], bv[8];
#pragma unroll
            for (int i = 0; i < 8; i++)
                av[i] = *reinterpret_cast<const ulonglong2*>(sA + (ty * 8 + i) * GPAD + (q << 2));
#pragma unroll
            for (int j = 0; j < 8; j++)
                bv[j] = *reinterpret_cast<const ulonglong2*>(sB + (tx + 16 * j) * GPAD + (q << 2));
#pragma unroll
            for (int i = 0; i < 8; i++)
#pragma unroll
                for (int j = 0; j < 8; j++) {
                    ffma2(acc2[i][j], av[i].x, bv[j].x);
                    ffma2(acc2[i][j], av[i].y, bv[j].y);
                }
        }
        __syncthreads();
    }

    // scatter into g_gx[t][l][g3][b][h]
#pragma unroll
    for (int jj = 0; jj < 8; jj++) {
        const int n  = ncol[jj];
        const int l  = n / 768;
        const int rr = n - l * 768;
        const int g3 = rr >> 8;
        const int h  = rr & 255;
#pragma unroll
        for (int ii = 0; ii < 8; ii++) {
            const int m = mbase + ty * 8 + ii;
            const int b = m >> 11;
            const int t = m & 2047;
            const size_t o =
                ((((size_t)t * LAY + l) * 3 + g3) * BSZ + b) * HID + h;
            g_gx[o] = hsum2(acc2[ii][jj]) + bias[jj];
        }
    }
}

// ---------------------------------------------------------------------------
// Kernel 2: cluster-persistent GRU scan.
// Dot: R7 mov-free k-pair f32x2, fully unrolled (weights stay in regs).
// Combine: Phase A (192 thr, 1 gate each) all sigmoids in parallel -> smem;
//          Phase B (128 thr, each a k-adjacent h-pair of one batch) tanh+mix,
//          v2 remote broadcast, out-store after cluster arrive.
// ---------------------------------------------------------------------------
#define SC_THREADS 256
#define PADK    260
#define SW3_F   (2 * 32 * PADK)                  // 16640 floats
#define PART_F  (4 * 192 * 2)                    //  1536 floats per half-plane
#define HBUF_F  (2 * 4 * 256)                    //  2048 floats

__device__ __forceinline__ void st_cluster_v2(uint32_t saddr, int trank, float v0, float v1)
{
    uint32_t ra;
    asm volatile("mapa.shared::cluster.u32 %0, %1, %2;" : "=r"(ra) : "r"(saddr), "r"(trank));
    asm volatile("st.shared::cluster.v2.f32 [%0], {%1, %2};" :: "r"(ra), "f"(v0), "f"(v1) : "memory");
}
__device__ __forceinline__ void cluster_arrive()
{ asm volatile("barrier.cluster.arrive.aligned;" ::: "memory"); }
__device__ __forceinline__ void cluster_wait()
{ asm volatile("barrier.cluster.wait.aligned;" ::: "memory"); }
__device__ __forceinline__ float sig_fast(float x) {
    return __fdividef(1.f, 1.f + __expf(-x));
}
__device__ __forceinline__ float tanh_fast(float x) {
    x = fminf(fmaxf(x, -15.f), 15.f);
    float e = __expf(2.f * x);
    return __fdividef(e - 1.f, e + 1.f);
}

__global__ void __cluster_dims__(4, 1, 1) __launch_bounds__(SC_THREADS, 1)
gru_scan_kernel(const float* __restrict__ Wh, const float* __restrict__ bh,
                float* __restrict__ out)
{
    extern __shared__ float sm[];
    float* sw3   = sm;                  // [64 rows][PADK]  (row2 weights)
    float* partA = sw3 + SW3_F;         // [4 kc][192 rr] float2 (b0,b1)
    float* partB = partA + PART_F;      // [4 kc][192 rr] float2 (b2,b3)
    float* hbuf  = partB + PART_F;      // [2 p][4 b][256 k]
    float* ex_r  = hbuf + HBUF_F;       // [4 b][64]
    float* ex_z  = ex_r + 256;          // [4 b][64]
    float* ex_xn = ex_z + 256;          // [4 b][64]
    float* ex_hn = ex_xn + 256;         // [4 b][64]

    const int tid  = threadIdx.x;
    const int lane = tid & 31;
    const int wid  = tid >> 5;
    const int rg   = wid >> 2;          // row group (96 rows)
    const int kc   = wid & 3;           // k-chunk
    const int k0   = kc << 6;

    const int rank = blockIdx.x & 3;
    const int cg   = blockIdx.x >> 2;
    const int g    = cg >> 3;
    const int c    = cg & 7;
    const int l    = g >> 1;
    const int dir  = g & 1;
    const int b0   = c * 4;

    // Phase-A identity (tid < 192): gate gi, lane li within gate
    const int gi = tid >> 6;
    const int li = tid & 63;
    const int hiA = rank * 64 + li;

    // Phase-B identity (tid < 128): batch bb, h-pair jj
    const int bbB = tid >> 5;           // 0..3
    const int jjB = tid & 31;           // h pair index
    const int hiB = rank * 64 + jjB * 2;

    const float* WhL = Wh + (size_t)l * 768 * 256;

    // 2 register weight rows as packed k-pairs (static indexing only)
    const int rrA = rg * 96 + lane * 3;
    ull w0r[32], w1r[32];
    {
        int r0 = rrA + 0, r1 = rrA + 1;
        const ull* p0 = reinterpret_cast<const ull*>(
            WhL + (size_t)((r0 >> 6) * 256 + rank * 64 + (r0 & 63)) * 256 + k0);
        const ull* p1 = reinterpret_cast<const ull*>(
            WhL + (size_t)((r1 >> 6) * 256 + rank * 64 + (r1 & 63)) * 256 + k0);
#pragma unroll
        for (int q = 0; q < 32; q++) { w0r[q] = p0[q]; w1r[q] = p1[q]; }
    }

    // 3rd-row weights: sw3[(rg*32+lane)][k]
    for (int i = tid; i < 2 * 32 * 256; i += SC_THREADS) {
        int ri = i >> 8;
        int k  = i & 255;
        int rg_ = ri >> 5;
        int ln  = ri & 31;
        int rr  = rg_ * 96 + ln * 3 + 2;
        sw3[ri * PADK + k] = WhL[(size_t)((rr >> 6) * 256 + rank * 64 + (rr & 63)) * 256 + k];
    }
    for (int i = tid; i < HBUF_F; i += SC_THREADS) hbuf[i] = 0.f;

    const float bhv = (tid < 192) ? bh[l * 768 + gi * 256 + hiA] : 0.f;

    __syncthreads();
    cluster_arrive(); cluster_wait();   // init visible cluster-wide
    cluster_arrive();                   // pre-arm for iter-0 wait

    const uint32_t hbuf_saddr = (uint32_t)__cvta_generic_to_shared(hbuf);
    const size_t gsz = (size_t)BSZ * HID;

    float hpe = 0.f, hpo = 0.f;         // phase-B h state (even/odd of pair)
    int p = 0;

    for (int step = 0; step < T_LEN; step++) {
        const int t = dir ? (T_LEN - 1 - step) : step;

        // gx prefetch for phase A (in flight across the barrier wait)
        float gx0, gx1, gx2, gx3;
        if (tid < 192) {
            const size_t base = ((size_t)t * LAY + l) * 3 * BSZ * HID
                              + (size_t)gi * gsz + (size_t)b0 * HID + hiA;
            gx0 = __ldg(g_gx + base);
            gx1 = __ldg(g_gx + base + HID);
            gx2 = __ldg(g_gx + base + 2 * HID);
            gx3 = __ldg(g_gx + base + 3 * HID);
        }

        cluster_wait();   // h(step-1) visible everywhere

        // --- dot: 3 rows x 4 batches over 64 k, k-pair packed, mov-free ---
        ull a00 = 0, a01 = 0, a02 = 0, a03 = 0;
        ull a10 = 0, a11 = 0, a12 = 0, a13 = 0;
        ull a20 = 0, a21 = 0, a22 = 0, a23 = 0;
        {
            const ulonglong2* h0p = reinterpret_cast<const ulonglong2*>(hbuf + ((p * 4 + 0) << 8) + k0);
            const ulonglong2* h1p = reinterpret_cast<const ulonglong2*>(hbuf + ((p * 4 + 1) << 8) + k0);
            const ulonglong2* h2p = reinterpret_cast<const ulonglong2*>(hbuf + ((p * 4 + 2) << 8) + k0);
            const ulonglong2* h3p = reinterpret_cast<const ulonglong2*>(hbuf + ((p * 4 + 3) << 8) + k0);
            const ulonglong2* w3p = reinterpret_cast<const ulonglong2*>(
                sw3 + (rg * 32 + lane) * PADK + k0);

#pragma unroll
            for (int q = 0; q < 16; q++) {
                const ulonglong2 w3 = w3p[q];
                const ulonglong2 hh0 = h0p[q];
                const ulonglong2 hh1 = h1p[q];
                const ulonglong2 hh2 = h2p[q];
                const ulonglong2 hh3 = h3p[q];
                const ull wa0 = w0r[2 * q], wa1 = w0r[2 * q + 1];
                const ull wb0 = w1r[2 * q], wb1 = w1r[2 * q + 1];
                ffma2(a00, wa0, hh0.x); ffma2(a00, wa1, hh0.y);
                ffma2(a01, wa0, hh1.x); ffma2(a01, wa1, hh1.y);
                ffma2(a02, wa0, hh2.x); ffma2(a02, wa1, hh2.y);
                ffma2(a03, wa0, hh3.x); ffma2(a03, wa1, hh3.y);
                ffma2(a10, wb0, hh0.x); ffma2(a10, wb1, hh0.y);
                ffma2(a11, wb0, hh1.x); ffma2(a11, wb1, hh1.y);
                ffma2(a12, wb0, hh2.x); ffma2(a12, wb1, hh2.y);
                ffma2(a13, wb0, hh3.x); ffma2(a13, wb1, hh3.y);
                ffma2(a20, w3.x, hh0.x); ffma2(a20, w3.y, hh0.y);
                ffma2(a21, w3.x, hh1.x); ffma2(a21, w3.y, hh1.y);
                ffma2(a22, w3.x, hh2.x); ffma2(a22, w3.y, hh2.y);
                ffma2(a23, w3.x, hh3.x); ffma2(a23, w3.y, hh3.y);
            }
        }
        {
            float2* pA = reinterpret_cast<float2*>(partA) + kc * 192 + rrA;
            float2* pB = reinterpret_cast<float2*>(partB) + kc * 192 + rrA;
            pA[0] = make_float2(hsum2(a00), hsum2(a01));
            pB[0] = make_float2(hsum2(a02), hsum2(a03));
            pA[1] = make_float2(hsum2(a10), hsum2(a11));
            pB[1] = make_float2(hsum2(a12), hsum2(a13));
            pA[2] = make_float2(hsum2(a20), hsum2(a21));
            pB[2] = make_float2(hsum2(a22), hsum2(a23));
        }
        __syncthreads();

        // --- Phase A: 192 threads (one gate each), all sigmoids in parallel ---
        if (tid < 192) {
            const float2* pA2 = reinterpret_cast<const float2*>(partA);
            const float2* pB2 = reinterpret_cast<const float2*>(partB);
            float2 q0 = pA2[tid], q1 = pA2[192 + tid], q2 = pA2[384 + tid], q3 = pA2[576 + tid];
            const float s0 = (q0.x + q1.x) + (q2.x + q3.x) + bhv;
            const float s1 = (q0.y + q1.y) + (q2.y + q3.y) + bhv;
            q0 = pB2[tid]; q1 = pB2[192 + tid]; q2 = pB2[384 + tid]; q3 = pB2[576 + tid];
            const float s2 = (q0.x + q1.x) + (q2.x + q3.x) + bhv;
            const float s3 = (q0.y + q1.y) + (q2.y + q3.y) + bhv;

            if (gi == 0) {
                ex_r[0 * 64 + li] = sig_fast(gx0 + s0);
                ex_r[1 * 64 + li] = sig_fast(gx1 + s1);
                ex_r[2 * 64 + li] = sig_fast(gx2 + s2);
                ex_r[3 * 64 + li] = sig_fast(gx3 + s3);
            } else if (gi == 1) {
                ex_z[0 * 64 + li] = sig_fast(gx0 + s0);
                ex_z[1 * 64 + li] = sig_fast(gx1 + s1);
                ex_z[2 * 64 + li] = sig_fast(gx2 + s2);
                ex_z[3 * 64 + li] = sig_fast(gx3 + s3);
            } else {
                ex_xn[0 * 64 + li] = gx0;  ex_hn[0 * 64 + li] = s0;
                ex_xn[1 * 64 + li] = gx1;  ex_hn[1 * 64 + li] = s1;
                ex_xn[2 * 64 + li] = gx2;  ex_hn[2 * 64 + li] = s2;
                ex_xn[3 * 64 + li] = gx3;  ex_hn[3 * 64 + li] = s3;
            }
        }
        __syncthreads();

        // --- Phase B: 128 threads, each a k-adjacent h-pair of one batch ---
        float hOutE = 0.f, hOutO = 0.f;
        if (tid < 128) {
            const int ei = bbB * 32 + jjB;     // float2 index into ex arrays
            const float2 rr2 = reinterpret_cast<const float2*>(ex_r)[ei];
            const float2 zz2 = reinterpret_cast<const float2*>(ex_z)[ei];
            const float2 xn2 = reinterpret_cast<const float2*>(ex_xn)[ei];
            const float2 hn2 = reinterpret_cast<const float2*>(ex_hn)[ei];

            const float nE = tanh_fast(xn2.x + rr2.x * hn2.x);
            const float nO = tanh_fast(xn2.y + rr2.y * hn2.y);
            hOutE = (1.f - zz2.x) * nE + zz2.x * hpe;
            hOutO = (1.f - zz2.y) * nO + zz2.y * hpo;
            hpe = hOutE; hpo = hOutO;

            // broadcast h pair into all 4 ranks' hbuf[1-p][bb][hiB..hiB+1]
            const uint32_t la = hbuf_saddr
                + (uint32_t)(((((1 - p) * 4 + bbB) << 8) + hiB) * 4);
            st_cluster_v2(la, 0, hOutE, hOutO);
            st_cluster_v2(la, 1, hOutE, hOutO);
            st_cluster_v2(la, 2, hOutE, hOutO);
            st_cluster_v2(la, 3, hOutE, hOutO);
        }

        cluster_arrive();   // release DSMEM stores; fences part/ex reuse

        if (tid < 128) {    // output store off the release path
            float2* po = reinterpret_cast<float2*>(
                out + (size_t)(b0 + bbB) * ((size_t)T_LEN * LAY * 2 * HID)
                    + ((size_t)t * LAY + l) * (2 * HID) + dir * HID + hiB);
            *po = make_float2(hOutE, hOutO);
        }
        p ^= 1;
    }
    cluster_wait();
}

// ---------------------------------------------------------------------------
extern "C" void kernel_launch(void* const* d_in, const int* in_sizes, int n_in,
                              void* d_out, int out_size)
{
    (void)in_sizes; (void)n_in; (void)out_size;
    const float* x  = (const float*)d_in[0];
    const float* Wx = (const float*)d_in[1];
    const float* Wh = (const float*)d_in[2];
    const float* bx = (const float*)d_in[3];
    const float* bh = (const float*)d_in[4];
    float* out = (float*)d_out;

    const int smem1 = 2 * 128 * GPAD * 4;                               // 69,632 B
    const int smem2 = (SW3_F + 2 * PART_F + HBUF_F + 4 * 256) * 4;      // 91,136 B

    cudaFuncSetAttribute(gx_gemm_kernel, cudaFuncAttributeMaxDynamicSharedMemorySize, smem1);
    cudaFuncSetAttribute(gru_scan_kernel, cudaFuncAttributeMaxDynamicSharedMemorySize, smem2);

    dim3 grid1(1536 / 128, 65536 / 128);   // 12 x 512 CTAs
    gx_gemm_kernel<<<grid1, 256, smem1>>>(x, Wx, bx);

    gru_scan_kernel<<<128, SC_THREADS, smem2>>>(Wh, bh, out);
}